// round 1
// baseline (speedup 1.0000x reference)
#include <cuda_runtime.h>
#include <cuda_bf16.h>

// Features2im: inverse 4x4 transform (analytic GK^{-1}) + 2x2 stride-1 fold
// (overlap-add) + count normalization, fully fused, output-stationary.
//
// Shapes: inputs 4x (B=4, C=64, H=512, W=512) fp32; output (4, 64, 513, 513) fp32.
//
// GK = D * H4 with H4 the symmetric Hadamard matrix, so
// GK^{-1} = (H4/4) * diag(4,-2,-2,-2):
//   g0 = a - .5b - .5c - .5d   -> (di=0, dj=0)
//   g1 = a + .5b - .5c + .5d   -> (0, 1)
//   g2 = a - .5b + .5c + .5d   -> (1, 0)
//   g3 = a + .5b + .5c - .5d   -> (1, 1)
// out[i,j] = (sum of valid g_{di,dj}(i-di, j-dj)) / count(i,j)

#define H_IN 512
#define W_IN 512
#define H_OUT 513
#define W_OUT 513
#define PLANE_IN (H_IN * W_IN)
#define PLANE_OUT (H_OUT * W_OUT)

__global__ __launch_bounds__(256) void features2im_kernel(
    const float* __restrict__ a,
    const float* __restrict__ b,
    const float* __restrict__ c,
    const float* __restrict__ d,
    float* __restrict__ out)
{
    int idx = blockIdx.x * 256 + threadIdx.x;      // index within one plane
    if (idx >= PLANE_OUT) return;
    int plane = blockIdx.y;                         // b*C + c, 0..255

    int i = idx / W_OUT;
    int j = idx - i * W_OUT;

    const float* pa = a + (size_t)plane * PLANE_IN;
    const float* pb = b + (size_t)plane * PLANE_IN;
    const float* pc = c + (size_t)plane * PLANE_IN;
    const float* pd = d + (size_t)plane * PLANE_IN;

    bool hv0 = (i < H_IN);   // row i valid as input row
    bool hv1 = (i >= 1);     // row i-1 valid
    bool wv0 = (j < W_IN);
    bool wv1 = (j >= 1);

    float acc = 0.0f;
    float cnt = 0.0f;

    // g0 at (i, j)
    if (hv0 && wv0) {
        int o = i * W_IN + j;
        acc += pa[o] - 0.5f * pb[o] - 0.5f * pc[o] - 0.5f * pd[o];
        cnt += 1.0f;
    }
    // g1 at (i, j-1)
    if (hv0 && wv1) {
        int o = i * W_IN + (j - 1);
        acc += pa[o] + 0.5f * pb[o] - 0.5f * pc[o] + 0.5f * pd[o];
        cnt += 1.0f;
    }
    // g2 at (i-1, j)
    if (hv1 && wv0) {
        int o = (i - 1) * W_IN + j;
        acc += pa[o] - 0.5f * pb[o] + 0.5f * pc[o] + 0.5f * pd[o];
        cnt += 1.0f;
    }
    // g3 at (i-1, j-1)
    if (hv1 && wv1) {
        int o = (i - 1) * W_IN + (j - 1);
        acc += pa[o] + 0.5f * pb[o] + 0.5f * pc[o] - 0.5f * pd[o];
        cnt += 1.0f;
    }

    out[(size_t)plane * PLANE_OUT + idx] = acc / cnt;
}

extern "C" void kernel_launch(void* const* d_in, const int* in_sizes, int n_in,
                              void* d_out, int out_size)
{
    const float* a = (const float*)d_in[0];
    const float* b = (const float*)d_in[1];
    const float* c = (const float*)d_in[2];
    const float* d = (const float*)d_in[3];
    float* out = (float*)d_out;

    dim3 block(256);
    dim3 grid((PLANE_OUT + 255) / 256, 256);  // 256 planes = B*C
    features2im_kernel<<<grid, block>>>(a, b, c, d, out);
}

// round 2
// speedup vs baseline: 1.0411x; 1.0411x over previous
#include <cuda_runtime.h>
#include <cuda_bf16.h>

// Features2im fused: analytic GK^{-1} + 2x2 stride-1 fold + count normalization.
//
// Per input row r:
//   u(r,j) = g0(r,j)+g1(r,j-1) = S - T
//   v(r,j) = g2(r,j)+g3(r,j-1) = S + T
//   S = (a_j + a_{j-1}) + 0.5*(b_{j-1} - b_j)
//   T = 0.5*(c_j + c_{j-1}) - 0.5*(d_{j-1} - d_j)
// out(i,j) = (u(i,j) + v(i-1,j)) * rinv(i) * cinv(j)
// with zero padding for out-of-range rows/cols; counts factorize as
// (#valid rows)*(#valid cols), rinv,cinv in {1, 0.5}.
//
// Thread layout: 128 threads/block, thread t owns columns 4t..4t+3 and loops
// over ROWS output rows, carrying v(i-1) in registers (each input element
// loaded exactly once per thread; j-1 neighbor via __shfl_up).

#define W_IN 512
#define H_IN 512
#define W_OUT 513
#define H_OUT 513
#define PLANE_IN (H_IN * W_IN)
#define PLANE_OUT (H_OUT * W_OUT)
#define ROWS 32

struct R5 { float l, x0, x1, x2, x3; };

__device__ __forceinline__ R5 load_row(const float* __restrict__ p, int r, int c0,
                                       int lane, bool valid)
{
    float4 q;
    if (valid) q = *reinterpret_cast<const float4*>(p + r * W_IN + c0);
    else       q = make_float4(0.f, 0.f, 0.f, 0.f);
    float left = __shfl_up_sync(0xffffffffu, q.w, 1);
    if (lane == 0) {
        left = (valid && c0 > 0) ? p[r * W_IN + c0 - 1] : 0.0f;
    }
    R5 v; v.l = left; v.x0 = q.x; v.x1 = q.y; v.x2 = q.z; v.x3 = q.w;
    return v;
}

__device__ __forceinline__ void compute_ST(const R5& a, const R5& b, const R5& c, const R5& d,
                                           float4& S, float4& T, float& S4, float& T4)
{
    S.x = (a.x0 + a.l)  + 0.5f * (b.l  - b.x0);
    S.y = (a.x1 + a.x0) + 0.5f * (b.x0 - b.x1);
    S.z = (a.x2 + a.x1) + 0.5f * (b.x1 - b.x2);
    S.w = (a.x3 + a.x2) + 0.5f * (b.x2 - b.x3);
    T.x = 0.5f * (c.x0 + c.l)  - 0.5f * (d.l  - d.x0);
    T.y = 0.5f * (c.x1 + c.x0) - 0.5f * (d.x0 - d.x1);
    T.z = 0.5f * (c.x2 + c.x1) - 0.5f * (d.x1 - d.x2);
    T.w = 0.5f * (c.x3 + c.x2) - 0.5f * (d.x2 - d.x3);
    // column j = 512 (x_j = 0, x_{j-1} = x3): only meaningful on thread 127
    S4 = a.x3 + 0.5f * b.x3;
    T4 = 0.5f * c.x3 - 0.5f * d.x3;
}

__global__ __launch_bounds__(128) void features2im_kernel(
    const float* __restrict__ A,
    const float* __restrict__ B,
    const float* __restrict__ C,
    const float* __restrict__ D,
    float* __restrict__ out)
{
    const int tid  = threadIdx.x;
    const int lane = tid & 31;
    const int c0   = tid << 2;
    const int plane = blockIdx.y;
    const int i0   = blockIdx.x * ROWS;
    const bool last_thread = (tid == 127);

    const float* pa = A + (size_t)plane * PLANE_IN;
    const float* pb = B + (size_t)plane * PLANE_IN;
    const float* pc = C + (size_t)plane * PLANE_IN;
    const float* pd = D + (size_t)plane * PLANE_IN;
    float* po = out + (size_t)plane * PLANE_OUT;

    const float ci0 = (c0 == 0) ? 1.0f : 0.5f;  // column inv-count for j=c0

    float4 vprev;            // v(i-1) for columns c0..c0+3
    float  vprev4 = 0.0f;    // v(i-1) for column 512 (thread 127)
    {
        const int r = i0 - 1;
        const bool valid = (i0 >= 1);
        R5 a = load_row(pa, r, c0, lane, valid);
        R5 b = load_row(pb, r, c0, lane, valid);
        R5 c = load_row(pc, r, c0, lane, valid);
        R5 d = load_row(pd, r, c0, lane, valid);
        float4 S, T; float S4, T4;
        compute_ST(a, b, c, d, S, T, S4, T4);
        vprev.x = S.x + T.x; vprev.y = S.y + T.y;
        vprev.z = S.z + T.z; vprev.w = S.w + T.w;
        vprev4  = S4 + T4;
        if (!valid) { vprev = make_float4(0.f,0.f,0.f,0.f); vprev4 = 0.f; }
    }

    const int iend = min(i0 + ROWS, H_OUT);
#pragma unroll 4
    for (int i = i0; i < iend; ++i) {
        const bool valid = (i < H_IN);
        R5 a = load_row(pa, i, c0, lane, valid);
        R5 b = load_row(pb, i, c0, lane, valid);
        R5 c = load_row(pc, i, c0, lane, valid);
        R5 d = load_row(pd, i, c0, lane, valid);
        float4 S, T; float S4, T4;
        compute_ST(a, b, c, d, S, T, S4, T4);

        const float rinv = (i >= 1 && i < H_IN) ? 0.5f : 1.0f;

        const size_t ob = (size_t)i * W_OUT + c0;
        po[ob + 0] = ((S.x - T.x) + vprev.x) * (rinv * ci0);
        po[ob + 1] = ((S.y - T.y) + vprev.y) * (rinv * 0.5f);
        po[ob + 2] = ((S.z - T.z) + vprev.z) * (rinv * 0.5f);
        po[ob + 3] = ((S.w - T.w) + vprev.w) * (rinv * 0.5f);
        if (last_thread) {
            po[(size_t)i * W_OUT + 512] = ((S4 - T4) + vprev4) * rinv;
        }

        vprev.x = S.x + T.x; vprev.y = S.y + T.y;
        vprev.z = S.z + T.z; vprev.w = S.w + T.w;
        vprev4  = S4 + T4;
    }
}

extern "C" void kernel_launch(void* const* d_in, const int* in_sizes, int n_in,
                              void* d_out, int out_size)
{
    const float* a = (const float*)d_in[0];
    const float* b = (const float*)d_in[1];
    const float* c = (const float*)d_in[2];
    const float* d = (const float*)d_in[3];
    float* out = (float*)d_out;

    dim3 block(128);
    dim3 grid((H_OUT + ROWS - 1) / ROWS, 256);  // 17 row-tiles x 256 planes
    features2im_kernel<<<grid, block>>>(a, b, c, d, out);
}

// round 3
// speedup vs baseline: 1.7187x; 1.6508x over previous
#include <cuda_runtime.h>
#include <cuda_bf16.h>

// Features2im fused: analytic GK^{-1} + 2x2 stride-1 fold + count normalization.
//
// Per input row r (zero-padded out of range):
//   S_j = (a_j + a_{j-1}) + 0.5*(b_{j-1} - b_j)
//   T_j = 0.5*(c_j + c_{j-1}) - 0.5*(d_{j-1} - d_j)
//   u = S - T (contribution to output row r), v = S + T (to output row r+1)
//   out(i,j) = (u(i,j) + v(i-1,j)) * rinv(i) * cinv(j)
//
// Thread t owns columns 4t..4t+3 (LDG.128 + one L1-hit scalar for j-1),
// walks 57 rows carrying v(i-1) in registers, depth-1 software pipeline
// (next row's 8 loads issued before current row's math) for MLP.

#define W_IN 512
#define H_IN 512
#define W_OUT 513
#define H_OUT 513
#define PLANE_IN (H_IN * W_IN)
#define PLANE_OUT (H_OUT * W_OUT)
#define ROWS 57   // 9 * 57 = 513, perfectly balanced row tiles

struct In5 { float l, x0, x1, x2, x3; };

__device__ __forceinline__ In5 ldrow(const float* __restrict__ p, int r, int c0, bool valid)
{
    In5 o;
    if (valid) {
        float4 q = *reinterpret_cast<const float4*>(p + r * W_IN + c0);
        o.x0 = q.x; o.x1 = q.y; o.x2 = q.z; o.x3 = q.w;
        o.l = (c0 != 0) ? p[r * W_IN + c0 - 1] : 0.0f;   // same 128B line as lane-1's vec -> L1 hit
    } else {
        o.l = o.x0 = o.x1 = o.x2 = o.x3 = 0.0f;
    }
    return o;
}

// S,T for 4 owned columns plus the trailing column (j = c0+4, uses x3 as left, 0 as self)
__device__ __forceinline__ void compute_ST(const In5& a, const In5& b, const In5& c, const In5& d,
                                           float4& S, float4& T, float& S4, float& T4)
{
    S.x = (a.x0 + a.l)  + 0.5f * (b.l  - b.x0);
    S.y = (a.x1 + a.x0) + 0.5f * (b.x0 - b.x1);
    S.z = (a.x2 + a.x1) + 0.5f * (b.x1 - b.x2);
    S.w = (a.x3 + a.x2) + 0.5f * (b.x2 - b.x3);
    T.x = 0.5f * (c.x0 + c.l)  + 0.5f * (d.x0 - d.l);
    T.y = 0.5f * (c.x1 + c.x0) + 0.5f * (d.x1 - d.x0);
    T.z = 0.5f * (c.x2 + c.x1) + 0.5f * (d.x2 - d.x1);
    T.w = 0.5f * (c.x3 + c.x2) + 0.5f * (d.x3 - d.x2);
    S4 = a.x3 + 0.5f * b.x3;           // only meaningful on thread 127 (column 512)
    T4 = 0.5f * c.x3 - 0.5f * d.x3;
}

__global__ __launch_bounds__(128) void features2im_kernel(
    const float* __restrict__ A,
    const float* __restrict__ B,
    const float* __restrict__ C,
    const float* __restrict__ D,
    float* __restrict__ out)
{
    const int tid   = threadIdx.x;
    const int c0    = tid << 2;
    const int plane = blockIdx.y;
    const int i0    = blockIdx.x * ROWS;
    const int iend  = min(i0 + ROWS, H_OUT);
    const bool last_thread = (tid == 127);

    const float* pa = A + (size_t)plane * PLANE_IN;
    const float* pb = B + (size_t)plane * PLANE_IN;
    const float* pc = C + (size_t)plane * PLANE_IN;
    const float* pd = D + (size_t)plane * PLANE_IN;
    float* po = out + (size_t)plane * PLANE_OUT;

    const float ci0 = (c0 == 0) ? 1.0f : 0.5f;   // column inv-count at j=c0

    // prologue: v(i0-1)
    float4 vprev; float vprev4;
    {
        const bool valid = (i0 >= 1);
        In5 a = ldrow(pa, i0 - 1, c0, valid);
        In5 b = ldrow(pb, i0 - 1, c0, valid);
        In5 c = ldrow(pc, i0 - 1, c0, valid);
        In5 d = ldrow(pd, i0 - 1, c0, valid);
        float4 S, T; float S4, T4;
        compute_ST(a, b, c, d, S, T, S4, T4);
        vprev.x = S.x + T.x; vprev.y = S.y + T.y;
        vprev.z = S.z + T.z; vprev.w = S.w + T.w;
        vprev4  = S4 + T4;
    }

    // pipeline stage: row i0 in flight
    In5 na = ldrow(pa, i0, c0, i0 < H_IN);
    In5 nb = ldrow(pb, i0, c0, i0 < H_IN);
    In5 nc = ldrow(pc, i0, c0, i0 < H_IN);
    In5 nd = ldrow(pd, i0, c0, i0 < H_IN);

#pragma unroll 2
    for (int i = i0; i < iend; ++i) {
        // issue next row's loads before touching current row's data
        const bool nvalid = (i + 1 < H_IN);
        In5 fa = ldrow(pa, i + 1, c0, nvalid);
        In5 fb = ldrow(pb, i + 1, c0, nvalid);
        In5 fc = ldrow(pc, i + 1, c0, nvalid);
        In5 fd = ldrow(pd, i + 1, c0, nvalid);

        float4 S, T; float S4, T4;
        compute_ST(na, nb, nc, nd, S, T, S4, T4);

        const float rinv = (i >= 1 && i < H_IN) ? 0.5f : 1.0f;
        const float rh = rinv * 0.5f;

        const size_t ob = (size_t)i * W_OUT + c0;
        po[ob + 0] = ((S.x - T.x) + vprev.x) * (rinv * ci0);
        po[ob + 1] = ((S.y - T.y) + vprev.y) * rh;
        po[ob + 2] = ((S.z - T.z) + vprev.z) * rh;
        po[ob + 3] = ((S.w - T.w) + vprev.w) * rh;
        if (last_thread) {
            po[(size_t)i * W_OUT + 512] = ((S4 - T4) + vprev4) * rinv;
        }

        vprev.x = S.x + T.x; vprev.y = S.y + T.y;
        vprev.z = S.z + T.z; vprev.w = S.w + T.w;
        vprev4  = S4 + T4;

        na = fa; nb = fb; nc = fc; nd = fd;
    }
}

extern "C" void kernel_launch(void* const* d_in, const int* in_sizes, int n_in,
                              void* d_out, int out_size)
{
    const float* a = (const float*)d_in[0];
    const float* b = (const float*)d_in[1];
    const float* c = (const float*)d_in[2];
    const float* d = (const float*)d_in[3];
    float* out = (float*)d_out;

    dim3 block(128);
    dim3 grid(9, 256);   // 9 row-tiles x 256 planes
    features2im_kernel<<<grid, block>>>(a, b, c, d, out);
}

// round 4
// speedup vs baseline: 1.7227x; 1.0023x over previous
#include <cuda_runtime.h>
#include <cuda_bf16.h>

// Features2im fused: analytic GK^{-1} + 2x2 stride-1 fold + count normalization.
//
// Per input row r (zero-padded out of range):
//   S_j = (a_j + a_{j-1}) + 0.5*(b_{j-1} - b_j)
//   T_j = 0.5*(c_j + c_{j-1}) + 0.5*(d_j - d_{j-1})
//   u = S - T (-> output row r), v = S + T (-> output row r+1)
//   out(i,j) = (u(i,j) + v(i-1,j)) * rinv(i) * cinv(j)
//
// Thread t owns columns 4t..4t+3 (one LDG.128 per input per row), walks 57
// rows carrying v(i-1) in registers. Depth-1 software pipeline: next row's
// loads are issued before current row's math. The j-1 neighbor comes from
// __shfl_up on already-resident registers (lane 0 uses a scalar load),
// halving L1 wavefront traffic vs redundant scalar loads.

#define W_IN 512
#define H_IN 512
#define W_OUT 513
#define H_OUT 513
#define PLANE_IN (H_IN * W_IN)
#define PLANE_OUT (H_OUT * W_OUT)
#define ROWS 57   // 9 * 57 = 513, perfectly balanced row tiles

struct RowRegs {
    float4 a, b, c, d;     // owned 4 columns for each input
    float la, lb, lc, ld;  // left-neighbor scalars (valid on lane 0 only)
};

__device__ __forceinline__ float4 ldvec(const float* __restrict__ p, int r, int c0, bool valid)
{
    if (valid) return *reinterpret_cast<const float4*>(p + r * W_IN + c0);
    return make_float4(0.f, 0.f, 0.f, 0.f);
}

__device__ __forceinline__ RowRegs load_row(const float* __restrict__ pa,
                                            const float* __restrict__ pb,
                                            const float* __restrict__ pc,
                                            const float* __restrict__ pd,
                                            int r, int c0, int lane, bool valid)
{
    RowRegs o;
    o.a = ldvec(pa, r, c0, valid);
    o.b = ldvec(pb, r, c0, valid);
    o.c = ldvec(pc, r, c0, valid);
    o.d = ldvec(pd, r, c0, valid);
    o.la = o.lb = o.lc = o.ld = 0.0f;
    if (lane == 0 && c0 != 0 && valid) {       // only 3 threads/block take this path
        int off = r * W_IN + c0 - 1;
        o.la = pa[off]; o.lb = pb[off]; o.lc = pc[off]; o.ld = pd[off];
    }
    return o;
}

// Resolve left neighbors via shfl (registers already resident), then compute
// S,T for the 4 owned columns plus trailing column c0+4 (thread 127 only).
__device__ __forceinline__ void compute_ST(const RowRegs& r, int lane,
                                           float4& S, float4& T, float& S4, float& T4)
{
    float al = __shfl_up_sync(0xffffffffu, r.a.w, 1);
    float bl = __shfl_up_sync(0xffffffffu, r.b.w, 1);
    float cl = __shfl_up_sync(0xffffffffu, r.c.w, 1);
    float dl = __shfl_up_sync(0xffffffffu, r.d.w, 1);
    if (lane == 0) { al = r.la; bl = r.lb; cl = r.lc; dl = r.ld; }

    S.x = (r.a.x + al)    + 0.5f * (bl    - r.b.x);
    S.y = (r.a.y + r.a.x) + 0.5f * (r.b.x - r.b.y);
    S.z = (r.a.z + r.a.y) + 0.5f * (r.b.y - r.b.z);
    S.w = (r.a.w + r.a.z) + 0.5f * (r.b.z - r.b.w);
    T.x = 0.5f * (r.c.x + cl)    + 0.5f * (r.d.x - dl);
    T.y = 0.5f * (r.c.y + r.c.x) + 0.5f * (r.d.y - r.d.x);
    T.z = 0.5f * (r.c.z + r.c.y) + 0.5f * (r.d.z - r.d.y);
    T.w = 0.5f * (r.c.w + r.c.z) + 0.5f * (r.d.w - r.d.z);
    S4 = r.a.w + 0.5f * r.b.w;         // column 512 (thread 127 only)
    T4 = 0.5f * r.c.w - 0.5f * r.d.w;
}

__global__ __launch_bounds__(128) void features2im_kernel(
    const float* __restrict__ A,
    const float* __restrict__ B,
    const float* __restrict__ C,
    const float* __restrict__ D,
    float* __restrict__ out)
{
    const int tid   = threadIdx.x;
    const int lane  = tid & 31;
    const int c0    = tid << 2;
    const int plane = blockIdx.y;
    const int i0    = blockIdx.x * ROWS;
    const int iend  = i0 + ROWS;          // 9*57 = 513 exactly, no tail
    const bool last_thread = (tid == 127);

    const float* pa = A + (size_t)plane * PLANE_IN;
    const float* pb = B + (size_t)plane * PLANE_IN;
    const float* pc = C + (size_t)plane * PLANE_IN;
    const float* pd = D + (size_t)plane * PLANE_IN;
    float* po = out + (size_t)plane * PLANE_OUT;

    const float ci0 = (c0 == 0) ? 1.0f : 0.5f;

    // prologue: v(i0-1)
    float4 vprev; float vprev4;
    {
        RowRegs r = load_row(pa, pb, pc, pd, i0 - 1, c0, lane, i0 >= 1);
        float4 S, T; float S4, T4;
        compute_ST(r, lane, S, T, S4, T4);
        vprev.x = S.x + T.x; vprev.y = S.y + T.y;
        vprev.z = S.z + T.z; vprev.w = S.w + T.w;
        vprev4  = S4 + T4;
    }

    // pipeline: row i0 loads in flight
    RowRegs cur = load_row(pa, pb, pc, pd, i0, c0, lane, i0 < H_IN);

#pragma unroll 3
    for (int i = i0; i < iend; ++i) {
        RowRegs nxt = load_row(pa, pb, pc, pd, i + 1, c0, lane, i + 1 < H_IN);

        float4 S, T; float S4, T4;
        compute_ST(cur, lane, S, T, S4, T4);

        const float rinv = (i >= 1 && i < H_IN) ? 0.5f : 1.0f;
        const float rh = rinv * 0.5f;

        const size_t ob = (size_t)i * W_OUT + c0;
        po[ob + 0] = ((S.x - T.x) + vprev.x) * (rinv * ci0);
        po[ob + 1] = ((S.y - T.y) + vprev.y) * rh;
        po[ob + 2] = ((S.z - T.z) + vprev.z) * rh;
        po[ob + 3] = ((S.w - T.w) + vprev.w) * rh;
        if (last_thread) {
            po[(size_t)i * W_OUT + 512] = ((S4 - T4) + vprev4) * rinv;
        }

        vprev.x = S.x + T.x; vprev.y = S.y + T.y;
        vprev.z = S.z + T.z; vprev.w = S.w + T.w;
        vprev4  = S4 + T4;

        cur = nxt;
    }
}

extern "C" void kernel_launch(void* const* d_in, const int* in_sizes, int n_in,
                              void* d_out, int out_size)
{
    const float* a = (const float*)d_in[0];
    const float* b = (const float*)d_in[1];
    const float* c = (const float*)d_in[2];
    const float* d = (const float*)d_in[3];
    float* out = (float*)d_out;

    dim3 block(128);
    dim3 grid(9, 256);   // 9 row-tiles x 256 planes
    features2im_kernel<<<grid, block>>>(a, b, c, d, out);
}